// round 10
// baseline (speedup 1.0000x reference)
#include <cuda_runtime.h>
#include <cstdint>
#include <cstddef>

// CosAttn2d: B=32, C=512, H=W=32, n_head=8, M=48  (shapes fixed by setup_inputs)
// bh = b*8 + head indexes 256 independent (batch, head) problems.
// qa = relu(q * 512^-0.25) + 1e-5 (same for k), v raw.
// coef_r[n] (n = h*32+w): r0=ch*cw, r1=ch*sw, r2=sh*cw, r3=sh*sw, angle = i*pi/96.
//
// Phase 1: ctx[k'=r*64+d][e] = sum_n coef_r[n]*ka[d,n]*v[e,n];  col 64 = ksum (v==1)
// Phase 2: out[e,n] = (sum_{k'} coef*qa * ctx[k'][e]) / (sum_{k'} coef*qa * ksum[k'])

#define HW      1024
#define DH      64
#define NBH     256
#define FREQ    0.0327249234748937f   // pi/96
#define DNORM   0.2102241038134286f   // 512^-0.25
#define EPS     1e-5f
#define CTX_LD  68                    // padded row (64 e + 1 ksum + pad for float4)

__device__ float g_ctx[NBH * 256 * CTX_LD];   // 17.8 MB scratch

// ---------------- Phase 1: ctx = K'^T V (one block per bh) ----------------
__global__ __launch_bounds__(256, 2)
void p1_kernel(const float* __restrict__ K, const float* __restrict__ V) {
    __shared__ float ks[64][65];   // [d][n], +1 pad -> bank = (d+n)%32
    __shared__ float vs[64][65];   // [e][n]
    __shared__ float cs[4][64];    // coef per r for current n-chunk

    const int bh = blockIdx.x;
    const int t  = threadIdx.x;
    const float* kb = K + (size_t)bh * (DH * HW);
    const float* vb = V + (size_t)bh * (DH * HW);

    const int ty = t >> 3;         // 0..31
    const int tx = t & 7;          // 0..7
    const int r  = ty >> 3;        // 0..3   (uniform per warp)
    const int dl = ty & 7;         // d = dl + 8*j  (lane-strided: conflict-free)
    // e = tx + 8*i (lane-strided: conflict-free)

    float acc[8][8];
    float ksa[8];
#pragma unroll
    for (int j = 0; j < 8; j++) {
        ksa[j] = 0.f;
#pragma unroll
        for (int i = 0; i < 8; i++) acc[j][i] = 0.f;
    }

    const int lr = t >> 4;           // load row base 0..15
    const int lc = (t & 15) << 2;    // load col 0..60

    for (int chunk = 0; chunk < 16; chunk++) {
        const int n0 = chunk << 6;
        __syncthreads();
#pragma unroll
        for (int it = 0; it < 4; it++) {
            const int row = lr + (it << 4);
            float4 kv = *(const float4*)(kb + row * HW + n0 + lc);
            ks[row][lc + 0] = fmaxf(kv.x * DNORM, 0.f) + EPS;
            ks[row][lc + 1] = fmaxf(kv.y * DNORM, 0.f) + EPS;
            ks[row][lc + 2] = fmaxf(kv.z * DNORM, 0.f) + EPS;
            ks[row][lc + 3] = fmaxf(kv.w * DNORM, 0.f) + EPS;
            float4 vv = *(const float4*)(vb + row * HW + n0 + lc);
            vs[row][lc + 0] = vv.x;
            vs[row][lc + 1] = vv.y;
            vs[row][lc + 2] = vv.z;
            vs[row][lc + 3] = vv.w;
        }
        if (t < 64) {
            const int n = n0 + t;
            float ch, sh, cw, sw;
            __sincosf((float)(n >> 5) * FREQ, &sh, &ch);
            __sincosf((float)(n & 31) * FREQ, &sw, &cw);
            cs[0][t] = ch * cw;
            cs[1][t] = ch * sw;
            cs[2][t] = sh * cw;
            cs[3][t] = sh * sw;
        }
        __syncthreads();
#pragma unroll 2
        for (int n = 0; n < 64; n++) {
            const float cf = cs[r][n];
            float a[8], bv[8];
#pragma unroll
            for (int j = 0; j < 8; j++) a[j] = ks[dl + (j << 3)][n] * cf;
#pragma unroll
            for (int i = 0; i < 8; i++) bv[i] = vs[tx + (i << 3)][n];
#pragma unroll
            for (int j = 0; j < 8; j++) {
                ksa[j] += a[j];
#pragma unroll
                for (int i = 0; i < 8; i++) acc[j][i] += a[j] * bv[i];
            }
        }
    }

    float* go = g_ctx + (size_t)bh * 256 * CTX_LD;
#pragma unroll
    for (int j = 0; j < 8; j++) {
        const int row = (r << 6) + dl + (j << 3);
#pragma unroll
        for (int i = 0; i < 8; i++)
            go[row * CTX_LD + tx + (i << 3)] = acc[j][i];
        if (tx == 0) go[row * CTX_LD + 64] = ksa[j];   // ksum column
    }
}

// ---------------- Phase 2: out = (Q' ctx) / D  (grid: 8 n-chunks x 256 bh) ----------------
__global__ __launch_bounds__(256, 2)
void p2_kernel(const float* __restrict__ Q, float* __restrict__ O) {
    __shared__ float qs[64][128];  // [d][n-chunk], float4-friendly, conflict-free

    const int bh = blockIdx.y;
    const int n0 = blockIdx.x << 7;       // 128-n chunk
    const int t  = threadIdx.x;
    const int te = t >> 5;                // 0..7 : e = te*8 + i  (warp-uniform)
    const int tn = t & 31;                // n = n0 + tn*4 + jj

    const float* qb  = Q + (size_t)bh * (DH * HW);
    float*       ob  = O + (size_t)bh * (DH * HW);
    const float* ctx = g_ctx + (size_t)bh * 256 * CTX_LD;

#pragma unroll
    for (int it = 0; it < 8; it++) {
        const int row = te + (it << 3);
        float4 qv = *(const float4*)(qb + row * HW + n0 + (tn << 2));
        float4 s;
        s.x = fmaxf(qv.x * DNORM, 0.f) + EPS;
        s.y = fmaxf(qv.y * DNORM, 0.f) + EPS;
        s.z = fmaxf(qv.z * DNORM, 0.f) + EPS;
        s.w = fmaxf(qv.w * DNORM, 0.f) + EPS;
        *(float4*)&qs[row][tn << 2] = s;
    }
    __syncthreads();

    float cf[4][4];
#pragma unroll
    for (int jj = 0; jj < 4; jj++) {
        const int n = n0 + (tn << 2) + jj;
        float ch, sh, cw, sw;
        __sincosf((float)(n >> 5) * FREQ, &sh, &ch);
        __sincosf((float)(n & 31) * FREQ, &sw, &cw);
        cf[0][jj] = ch * cw;
        cf[1][jj] = ch * sw;
        cf[2][jj] = sh * cw;
        cf[3][jj] = sh * sw;
    }

    float acc[8][4];
    float Da[4] = {0.f, 0.f, 0.f, 0.f};
#pragma unroll
    for (int i = 0; i < 8; i++)
#pragma unroll
        for (int jj = 0; jj < 4; jj++) acc[i][jj] = 0.f;

#pragma unroll
    for (int r = 0; r < 4; r++) {
        const float c0f = cf[r][0], c1f = cf[r][1], c2f = cf[r][2], c3f = cf[r][3];
        const float* crow = ctx + (size_t)(r << 6) * CTX_LD;
#pragma unroll 4
        for (int d = 0; d < 64; d++) {
            float4 a4 = *(const float4*)&qs[(r << 6) ? ((r << 6) + d - (r << 6)) : d][tn << 2]; // d row
            // (index is just d; written plainly below to avoid confusion)
            a4 = *(const float4*)&qs[d][tn << 2];
            const float ap0 = a4.x * c0f;
            const float ap1 = a4.y * c1f;
            const float ap2 = a4.z * c2f;
            const float ap3 = a4.w * c3f;
            const float4 cA = *(const float4*)(crow + (te << 3));
            const float4 cB = *(const float4*)(crow + (te << 3) + 4);
            const float ksv = crow[64];
            const float cc[8] = {cA.x, cA.y, cA.z, cA.w, cB.x, cB.y, cB.z, cB.w};
#pragma unroll
            for (int i = 0; i < 8; i++) {
                acc[i][0] += cc[i] * ap0;
                acc[i][1] += cc[i] * ap1;
                acc[i][2] += cc[i] * ap2;
                acc[i][3] += cc[i] * ap3;
            }
            Da[0] += ksv * ap0;
            Da[1] += ksv * ap1;
            Da[2] += ksv * ap2;
            Da[3] += ksv * ap3;
            crow += CTX_LD;
        }
    }

    float rin[4];
#pragma unroll
    for (int jj = 0; jj < 4; jj++) rin[jj] = 1.0f / Da[jj];
#pragma unroll
    for (int i = 0; i < 8; i++) {
        float4 o;
        o.x = acc[i][0] * rin[0];
        o.y = acc[i][1] * rin[1];
        o.z = acc[i][2] * rin[2];
        o.w = acc[i][3] * rin[3];
        *(float4*)(ob + (size_t)((te << 3) + i) * HW + n0 + (tn << 2)) = o;
    }
}

extern "C" void kernel_launch(void* const* d_in, const int* in_sizes, int n_in,
                              void* d_out, int out_size) {
    (void)in_sizes; (void)n_in; (void)out_size;
    const float* q = (const float*)d_in[0];
    const float* k = (const float*)d_in[1];
    const float* v = (const float*)d_in[2];
    float* o = (float*)d_out;

    p1_kernel<<<NBH, 256>>>(k, v);
    p2_kernel<<<dim3(8, NBH), 256>>>(q, o);
}